// round 14
// baseline (speedup 1.0000x reference)
#include <cuda_runtime.h>
#include <math.h>

#define NN   100000
#define EE   1600000
#define FIN  128
#define FOUT 64
#define THRESH 0.48f
#define MAXN   (1.0f - 4e-3f)

#define SCAN_B 1024
#define NBLK   ((NN + SCAN_B - 1) / SCAN_B)   // 98

#define GEMM_ROWS   32
#define GEMM_TPB    128
#define GEMM_BLOCKS (NN / GEMM_ROWS)          // 3125 (exact)

#define AGG_BLOCKS  ((NN * 32 + 255) / 256)   // 12500
#define CZERO_BLOCKS ((NN + 255) / 256)       // 391 tail blocks on aggA

typedef unsigned long long u64;

// -------- scratch (device globals; zero-initialized at load) --------
__device__ float  g_updated [NN * FOUT];
__device__ float4 g_e       [NN];   // (u.wpl0, u.wpl1, u.wlw_hi, u.wlw_lo)
__device__ float  g_b1      [NN];   // sum_j dot(u[j], wlw_hi)
__device__ float  g_sel     [NN];   // 0/1 hard gate
__device__ float  g_selD    [NN];   // sel * dot(u, wlw_lo)
__device__ float  g_gate    [NN];   // weight_sel * sel
__device__ int    g_rowptr  [NN + 1];
__device__ int    g_cursor  [NN];   // self-restoring: re-zeroed by aggA tail
__device__ int    g_col     [EE];
__device__ int    g_blocksum[NBLK];

// ---- f32x2 helpers ----
__device__ __forceinline__ u64 pack2(float lo, float hi) {
    u64 r; asm("mov.b64 %0,{%1,%2};" : "=l"(r) : "f"(lo), "f"(hi)); return r;
}
__device__ __forceinline__ void unpack2(u64 v, float& lo, float& hi) {
    asm("mov.b64 {%0,%1},%2;" : "=f"(lo), "=f"(hi) : "l"(v));
}
__device__ __forceinline__ u64 add2(u64 a, u64 b) {
    u64 d; asm("add.rn.f32x2 %0,%1,%2;" : "=l"(d) : "l"(a), "l"(b)); return d;
}
__device__ __forceinline__ u64 fma2(u64 a, u64 b, u64 c) {
    u64 d; asm("fma.rn.f32x2 %0,%1,%2,%3;" : "=l"(d) : "l"(a), "l"(b), "l"(c)); return d;
}

// ---------------------------------------------------------------------------
// K1: logmap0 (in-place on x tile) + GEMM + leaky_relu + projection epilogue.
// Runs on a side stream, concurrent with the CSR build chain.
// ---------------------------------------------------------------------------
__global__ void __launch_bounds__(GEMM_TPB) k_up(const float* __restrict__ x,
                                                 const float* __restrict__ Wup,
                                                 const float* __restrict__ Wpl,
                                                 const float* __restrict__ Wlw) {
    __shared__ float  xs[GEMM_ROWS][FIN];   // 16 KB
    __shared__ float4 Ws[FIN * 16];         // 32 KB

    int t = threadIdx.x;
    int rbase = blockIdx.x * GEMM_ROWS;

    const float4* W4 = (const float4*)Wup;
    #pragma unroll
    for (int i = t; i < FIN * 16; i += GEMM_TPB) Ws[i] = W4[i];
    const float4* x4 = (const float4*)(x + (size_t)rbase * FIN);
    float4* xs4 = (float4*)xs;
    #pragma unroll
    for (int i = t; i < GEMM_ROWS * FIN / 4; i += GEMM_TPB) xs4[i] = x4[i];
    __syncthreads();

    int w = t >> 5, lane = t & 31;
    #pragma unroll
    for (int rr = 0; rr < 8; ++rr) {
        int r = w * 8 + rr;
        float4 v = ((float4*)xs[r])[lane];
        float s = v.x * v.x + v.y * v.y + v.z * v.z + v.w * v.w;
        #pragma unroll
        for (int o = 16; o; o >>= 1) s += __shfl_xor_sync(0xffffffffu, s, o);
        float n = fmaxf(sqrtf(s), 1e-15f);
        float a = fminf(fmaxf(n, -1.0f + 1e-7f), 1.0f - 1e-7f);
        float art = 0.5f * (log1pf(a) - log1pf(-a));
        float sc = art / n;
        v.x *= sc; v.y *= sc; v.z *= sc; v.w *= sc;
        ((float4*)xs[r])[lane] = v;
    }
    __syncthreads();

    int cg = t & 15;
    int rg = t >> 4;
    u64 acc[4][2];
    #pragma unroll
    for (int i = 0; i < 4; ++i) { acc[i][0] = 0; acc[i][1] = 0; }

    #pragma unroll 2
    for (int k = 0; k < FIN; k += 4) {
        float4 xv[4];
        #pragma unroll
        for (int i = 0; i < 4; ++i)
            xv[i] = *(const float4*)&xs[rg + 8 * i][k];
        #pragma unroll
        for (int q = 0; q < 4; ++q) {
            float4 wv = Ws[(k + q) * 16 + cg];
            u64 w01 = pack2(wv.x, wv.y);
            u64 w23 = pack2(wv.z, wv.w);
            #pragma unroll
            for (int i = 0; i < 4; ++i) {
                float xq = (q == 0) ? xv[i].x : (q == 1) ? xv[i].y
                         : (q == 2) ? xv[i].z : xv[i].w;
                u64 xx = pack2(xq, xq);
                acc[i][0] = fma2(xx, w01, acc[i][0]);
                acc[i][1] = fma2(xx, w23, acc[i][1]);
            }
        }
    }

    float4 we[4];
    #pragma unroll
    for (int m = 0; m < 4; ++m) {
        int c = cg * 4 + m;
        we[m] = make_float4(__ldg(&Wpl[2 * c]), __ldg(&Wpl[2 * c + 1]),
                            __ldg(&Wlw[64 + c]), __ldg(&Wlw[c]));
    }

    #pragma unroll
    for (int i = 0; i < 4; ++i) {
        int r = rg + 8 * i;
        float c0, c1, c2, c3;
        unpack2(acc[i][0], c0, c1);
        unpack2(acc[i][1], c2, c3);
        float4 o;
        o.x = c0 > 0.f ? c0 : 0.01f * c0;
        o.y = c1 > 0.f ? c1 : 0.01f * c1;
        o.z = c2 > 0.f ? c2 : 0.01f * c2;
        o.w = c3 > 0.f ? c3 : 0.01f * c3;
        ((float4*)g_updated)[(size_t)(rbase + r) * 16 + cg] = o;

        float d0 = o.x * we[0].x + o.y * we[1].x + o.z * we[2].x + o.w * we[3].x;
        float d1 = o.x * we[0].y + o.y * we[1].y + o.z * we[2].y + o.w * we[3].y;
        float d2 = o.x * we[0].z + o.y * we[1].z + o.z * we[2].z + o.w * we[3].z;
        float d3 = o.x * we[0].w + o.y * we[1].w + o.z * we[2].w + o.w * we[3].w;
        #pragma unroll
        for (int off = 8; off; off >>= 1) {
            d0 += __shfl_xor_sync(0xffffffffu, d0, off);
            d1 += __shfl_xor_sync(0xffffffffu, d1, off);
            d2 += __shfl_xor_sync(0xffffffffu, d2, off);
            d3 += __shfl_xor_sync(0xffffffffu, d3, off);
        }
        if (cg == 0) g_e[rbase + r] = make_float4(d0, d1, d2, d3);
    }
}

// ---------------------------------------------------------------------------
// CSR build (g_cursor arrives zeroed: initial load zero-init, then restored
// by aggA's tail blocks every call)
// ---------------------------------------------------------------------------
__global__ void k_hist(const int* __restrict__ ei) {
    int t = blockIdx.x * blockDim.x + threadIdx.x;
    if (t < EE) atomicAdd(&g_cursor[ei[EE + t]], 1);
}

__global__ void __launch_bounds__(SCAN_B) k_scan1() {
    __shared__ int wsum[32];
    int t = threadIdx.x, b = blockIdx.x;
    int idx = b * SCAN_B + t;
    int lane = t & 31, w = t >> 5;
    int c = (idx < NN) ? g_cursor[idx] : 0;
    int v = c;
    #pragma unroll
    for (int o = 1; o < 32; o <<= 1) {
        int n = __shfl_up_sync(0xffffffffu, v, o);
        if (lane >= o) v += n;
    }
    if (lane == 31) wsum[w] = v;
    __syncthreads();
    if (w == 0) {
        int s = wsum[lane];
        #pragma unroll
        for (int o = 1; o < 32; o <<= 1) {
            int n = __shfl_up_sync(0xffffffffu, s, o);
            if (lane >= o) s += n;
        }
        wsum[lane] = s;
    }
    __syncthreads();
    int base = (w > 0) ? wsum[w - 1] : 0;
    int incl = v + base;
    if (idx < NN) g_rowptr[idx] = incl - c;
    if (t == SCAN_B - 1) g_blocksum[b] = incl;
}

__global__ void __launch_bounds__(SCAN_B) k_scan3() {
    __shared__ int s[128];
    int t = threadIdx.x;
    if (t < 128) s[t] = (t < NBLK) ? g_blocksum[t] : 0;
    __syncthreads();
    #pragma unroll
    for (int o = 1; o < 128; o <<= 1) {
        int a = 0;
        if (t < 128 && t >= o) a = s[t - o];
        __syncthreads();
        if (t < 128) s[t] += a;
        __syncthreads();
    }
    int off = (blockIdx.x == 0) ? 0 : s[blockIdx.x - 1];
    int idx = blockIdx.x * SCAN_B + t;
    if (idx < NN) {
        int r = g_rowptr[idx] + off;
        g_rowptr[idx] = r;
        g_cursor[idx] = r;
    }
    if (idx == 0) g_rowptr[NN] = EE;
}

__global__ void k_fill(const int* __restrict__ ei) {
    int t = blockIdx.x * blockDim.x + threadIdx.x;
    if (t < EE) {
        int d = ei[EE + t];
        int p = atomicAdd(&g_cursor[d], 1);
        g_col[p] = ei[t];
    }
}

// ---------------------------------------------------------------------------
// Pass A: lane-per-edge gather of 16B projections; sel + selD + b1 epilogue.
// Tail blocks re-zero g_cursor for the next graph replay (fill was its last
// reader; aggA is ordered after fill).
// ---------------------------------------------------------------------------
__global__ void __launch_bounds__(256) k_aggA() {
    if (blockIdx.x >= AGG_BLOCKS) {
        int i = (blockIdx.x - AGG_BLOCKS) * 256 + threadIdx.x;
        if (i < NN) g_cursor[i] = 0;
        return;
    }
    int gw = (blockIdx.x * blockDim.x + threadIdx.x) >> 5;
    int lane = threadIdx.x & 31;
    if (gw >= NN) return;
    int s = g_rowptr[gw], e = g_rowptr[gw + 1];
    float s0 = 0.f, s1 = 0.f, s2 = 0.f;
    for (int p = s + lane; p < e; p += 32) {
        int j = __ldg(&g_col[p]);
        float4 ev = __ldg(&g_e[j]);
        s0 += ev.x; s1 += ev.y; s2 += ev.z;
    }
    #pragma unroll
    for (int o = 16; o; o >>= 1) {
        s0 += __shfl_xor_sync(0xffffffffu, s0, o);
        s1 += __shfl_xor_sync(0xffffffffu, s1, o);
        s2 += __shfl_xor_sync(0xffffffffu, s2, o);
    }
    if (lane == 0) {
        float r0 = fmaxf(s0, 0.f), r1 = fmaxf(s1, 0.f);
        float p1 = 1.0f / (1.0f + expf(r0 - r1));
        float sel = (p1 > THRESH) ? 1.0f : 0.0f;
        g_sel[gw]  = sel;
        g_b1[gw]   = s2;
        float d    = __ldg(&g_e[gw]).w;
        g_selD[gw] = sel * d;
    }
}

// ---------------------------------------------------------------------------
// Pass B: z = sum_j selD[j] + b1[i]; gate = sigmoid(z) * sel[i]. 4B gathers.
// ---------------------------------------------------------------------------
__global__ void __launch_bounds__(256) k_aggB() {
    int gw = (blockIdx.x * blockDim.x + threadIdx.x) >> 5;
    int lane = threadIdx.x & 31;
    if (gw >= NN) return;
    int s = g_rowptr[gw], e = g_rowptr[gw + 1];
    float z = 0.f;
    for (int p = s + lane; p < e; p += 32)
        z += __ldg(&g_selD[__ldg(&g_col[p])]);
    #pragma unroll
    for (int o = 16; o; o >>= 1) z += __shfl_xor_sync(0xffffffffu, z, o);
    if (lane == 0) {
        z += g_b1[gw];
        float ws = 1.0f / (1.0f + expf(-z));
        g_gate[gw] = ws * g_sel[gw];
    }
}

// ---------------------------------------------------------------------------
// Pass C: edge-paired half-warp gather (proven structure, unchanged).
// ---------------------------------------------------------------------------
__global__ void __launch_bounds__(256) k_aggC(float* __restrict__ out) {
    int gw = (blockIdx.x * blockDim.x + threadIdx.x) >> 5;
    int lane = threadIdx.x & 31;
    if (gw >= NN) return;
    int s = g_rowptr[gw], e = g_rowptr[gw + 1];
    const float4* U4 = (const float4*)g_updated;
    int half = lane >> 4;
    int hl   = lane & 15;
    u64 acc0 = 0, acc1 = 0;

    for (int base = s; base < e; base += 32) {
        int cnt = e - base; if (cnt > 32) cnt = 32;
        int jreg = 0; float greg = 0.f;
        if (lane < cnt) {
            jreg = __ldg(&g_col[base + lane]);
            greg = __ldg(&g_gate[jreg]);
        }
        int cnt2 = (cnt + 1) & ~1;
        for (int q = 0; q < cnt2; q += 2) {
            int myq = q + half;
            int   j = __shfl_sync(0xffffffffu, jreg, myq);
            float g = __shfl_sync(0xffffffffu, greg, myq);
            if (g != 0.f) {
                float4 u = __ldg(&U4[(size_t)j * 16 + hl]);
                u64 gg = pack2(g, g);
                acc0 = fma2(gg, pack2(u.x, u.y), acc0);
                acc1 = fma2(gg, pack2(u.z, u.w), acc1);
            }
        }
    }
    acc0 = add2(acc0, __shfl_xor_sync(0xffffffffu, acc0, 16));
    acc1 = add2(acc1, __shfl_xor_sync(0xffffffffu, acc1, 16));
    float a0, a1, a2, a3;
    unpack2(acc0, a0, a1);
    unpack2(acc1, a2, a3);

    float4 ui = __ldg(&U4[(size_t)gw * 16 + hl]);
    float o0 = ui.x + fmaxf(a0, 0.f);
    float o1 = ui.y + fmaxf(a1, 0.f);
    float o2 = ui.z + fmaxf(a2, 0.f);
    float o3 = ui.w + fmaxf(a3, 0.f);
    float ss = o0 * o0 + o1 * o1 + o2 * o2 + o3 * o3;
    #pragma unroll
    for (int o = 8; o; o >>= 1) ss += __shfl_xor_sync(0xffffffffu, ss, o);
    float n = fmaxf(sqrtf(ss), 1e-15f);
    float th = tanhf(n);
    float f = (th > MAXN) ? (MAXN / n) : (th / n);
    if (half == 0)
        ((float4*)out)[(size_t)gw * 16 + hl] =
            make_float4(o0 * f, o1 * f, o2 * f, o3 * f);
}

// ---------------------------------------------------------------------------
extern "C" void kernel_launch(void* const* d_in, const int* in_sizes, int n_in,
                              void* d_out, int out_size) {
    const float* x   = (const float*)d_in[0];
    const int*   ei  = (const int*)  d_in[1];
    const float* Wup = (const float*)d_in[2];
    const float* Wpl = (const float*)d_in[3];
    const float* Wlw = (const float*)d_in[4];
    float* out = (float*)d_out;

    (void)in_sizes; (void)n_in; (void)out_size;

    // One-time stream/event setup (host objects only; no device allocation).
    static cudaStream_t s2 = nullptr;
    static cudaEvent_t  evFork = nullptr, evJoin = nullptr;
    if (s2 == nullptr) {
        cudaStreamCreateWithFlags(&s2, cudaStreamNonBlocking);
        cudaEventCreateWithFlags(&evFork, cudaEventDisableTiming);
        cudaEventCreateWithFlags(&evJoin, cudaEventDisableTiming);
    }

    // Fork: GEMM branch runs concurrently with the CSR-build branch.
    cudaEventRecord(evFork, 0);
    cudaStreamWaitEvent(s2, evFork, 0);
    k_up<<<GEMM_BLOCKS, GEMM_TPB, 0, s2>>>(x, Wup, Wpl, Wlw);
    cudaEventRecord(evJoin, s2);

    // CSR chain on the main (captured) stream.
    k_hist<<<(EE + 255) / 256, 256>>>(ei);
    k_scan1<<<NBLK, SCAN_B>>>();
    k_scan3<<<NBLK, SCAN_B>>>();
    k_fill<<<(EE + 255) / 256, 256>>>(ei);

    // Join: aggA needs g_e from k_up (and CSR from fill).
    cudaStreamWaitEvent(0, evJoin, 0);
    k_aggA<<<AGG_BLOCKS + CZERO_BLOCKS, 256>>>();
    k_aggB<<<AGG_BLOCKS, 256>>>();
    k_aggC<<<AGG_BLOCKS, 256>>>(out);
}

// round 15
// speedup vs baseline: 1.0595x; 1.0595x over previous
#include <cuda_runtime.h>
#include <math.h>

#define NN   100000
#define EE   1600000
#define FIN  128
#define FOUT 64
#define THRESH 0.48f
#define MAXN   (1.0f - 4e-3f)

#define SCAN_B 1024
#define NBLK   ((NN + SCAN_B - 1) / SCAN_B)   // 98

#define GEMM_ROWS   32
#define GEMM_TPB    128
#define GEMM_BLOCKS (NN / GEMM_ROWS)          // 3125 (exact)

#define FILL_BLOCKS ((EE + 255) / 256)        // 6250
#define AGG16_BLOCKS ((NN * 16 + 255) / 256)  // 6250 (two nodes/warp passes)
#define AGG32_BLOCKS ((NN * 32 + 255) / 256)  // 12500 (pass C)
#define CZERO_BLOCKS ((NN + 255) / 256)       // 391 tail blocks on aggA

typedef unsigned long long u64;

// -------- scratch (device globals; zero-initialized at load) --------
__device__ float  g_updated [NN * FOUT];
__device__ float4 g_e       [NN];   // (u.wpl0, u.wpl1, u.wlw_hi, u.wlw_lo)
__device__ float  g_b1      [NN];
__device__ float  g_sel     [NN];
__device__ float  g_selD    [NN];
__device__ float  g_gate    [NN];
__device__ int    g_rowptr  [NN + 1];
__device__ int    g_cursor  [NN];   // self-restoring: zeroed by aggA tail
__device__ int    g_col     [EE];
__device__ int    g_agg     [NBLK]; // scan lookback aggregates
__device__ int    g_flag    [NBLK]; // self-restoring: zeroed by fill tail

// ---- f32x2 helpers ----
__device__ __forceinline__ u64 pack2(float lo, float hi) {
    u64 r; asm("mov.b64 %0,{%1,%2};" : "=l"(r) : "f"(lo), "f"(hi)); return r;
}
__device__ __forceinline__ void unpack2(u64 v, float& lo, float& hi) {
    asm("mov.b64 {%0,%1},%2;" : "=f"(lo), "=f"(hi) : "l"(v));
}
__device__ __forceinline__ u64 add2(u64 a, u64 b) {
    u64 d; asm("add.rn.f32x2 %0,%1,%2;" : "=l"(d) : "l"(a), "l"(b)); return d;
}
__device__ __forceinline__ u64 fma2(u64 a, u64 b, u64 c) {
    u64 d; asm("fma.rn.f32x2 %0,%1,%2,%3;" : "=l"(d) : "l"(a), "l"(b), "l"(c)); return d;
}

// ---------------------------------------------------------------------------
// K1: logmap0 (in-place on x tile) + GEMM + leaky_relu + projection epilogue.
// ---------------------------------------------------------------------------
__global__ void __launch_bounds__(GEMM_TPB) k_up(const float* __restrict__ x,
                                                 const float* __restrict__ Wup,
                                                 const float* __restrict__ Wpl,
                                                 const float* __restrict__ Wlw) {
    __shared__ float  xs[GEMM_ROWS][FIN];   // 16 KB
    __shared__ float4 Ws[FIN * 16];         // 32 KB

    int t = threadIdx.x;
    int rbase = blockIdx.x * GEMM_ROWS;

    const float4* W4 = (const float4*)Wup;
    #pragma unroll
    for (int i = t; i < FIN * 16; i += GEMM_TPB) Ws[i] = W4[i];
    const float4* x4 = (const float4*)(x + (size_t)rbase * FIN);
    float4* xs4 = (float4*)xs;
    #pragma unroll
    for (int i = t; i < GEMM_ROWS * FIN / 4; i += GEMM_TPB) xs4[i] = x4[i];
    __syncthreads();

    int w = t >> 5, lane = t & 31;
    #pragma unroll
    for (int rr = 0; rr < 8; ++rr) {
        int r = w * 8 + rr;
        float4 v = ((float4*)xs[r])[lane];
        float s = v.x * v.x + v.y * v.y + v.z * v.z + v.w * v.w;
        #pragma unroll
        for (int o = 16; o; o >>= 1) s += __shfl_xor_sync(0xffffffffu, s, o);
        float n = fmaxf(sqrtf(s), 1e-15f);
        float a = fminf(fmaxf(n, -1.0f + 1e-7f), 1.0f - 1e-7f);
        float art = 0.5f * (log1pf(a) - log1pf(-a));
        float sc = art / n;
        v.x *= sc; v.y *= sc; v.z *= sc; v.w *= sc;
        ((float4*)xs[r])[lane] = v;
    }
    __syncthreads();

    int cg = t & 15;
    int rg = t >> 4;
    u64 acc[4][2];
    #pragma unroll
    for (int i = 0; i < 4; ++i) { acc[i][0] = 0; acc[i][1] = 0; }

    #pragma unroll 2
    for (int k = 0; k < FIN; k += 4) {
        float4 xv[4];
        #pragma unroll
        for (int i = 0; i < 4; ++i)
            xv[i] = *(const float4*)&xs[rg + 8 * i][k];
        #pragma unroll
        for (int q = 0; q < 4; ++q) {
            float4 wv = Ws[(k + q) * 16 + cg];
            u64 w01 = pack2(wv.x, wv.y);
            u64 w23 = pack2(wv.z, wv.w);
            #pragma unroll
            for (int i = 0; i < 4; ++i) {
                float xq = (q == 0) ? xv[i].x : (q == 1) ? xv[i].y
                         : (q == 2) ? xv[i].z : xv[i].w;
                u64 xx = pack2(xq, xq);
                acc[i][0] = fma2(xx, w01, acc[i][0]);
                acc[i][1] = fma2(xx, w23, acc[i][1]);
            }
        }
    }

    float4 we[4];
    #pragma unroll
    for (int m = 0; m < 4; ++m) {
        int c = cg * 4 + m;
        we[m] = make_float4(__ldg(&Wpl[2 * c]), __ldg(&Wpl[2 * c + 1]),
                            __ldg(&Wlw[64 + c]), __ldg(&Wlw[c]));
    }

    #pragma unroll
    for (int i = 0; i < 4; ++i) {
        int r = rg + 8 * i;
        float c0, c1, c2, c3;
        unpack2(acc[i][0], c0, c1);
        unpack2(acc[i][1], c2, c3);
        float4 o;
        o.x = c0 > 0.f ? c0 : 0.01f * c0;
        o.y = c1 > 0.f ? c1 : 0.01f * c1;
        o.z = c2 > 0.f ? c2 : 0.01f * c2;
        o.w = c3 > 0.f ? c3 : 0.01f * c3;
        ((float4*)g_updated)[(size_t)(rbase + r) * 16 + cg] = o;

        float d0 = o.x * we[0].x + o.y * we[1].x + o.z * we[2].x + o.w * we[3].x;
        float d1 = o.x * we[0].y + o.y * we[1].y + o.z * we[2].y + o.w * we[3].y;
        float d2 = o.x * we[0].z + o.y * we[1].z + o.z * we[2].z + o.w * we[3].z;
        float d3 = o.x * we[0].w + o.y * we[1].w + o.z * we[2].w + o.w * we[3].w;
        #pragma unroll
        for (int off = 8; off; off >>= 1) {
            d0 += __shfl_xor_sync(0xffffffffu, d0, off);
            d1 += __shfl_xor_sync(0xffffffffu, d1, off);
            d2 += __shfl_xor_sync(0xffffffffu, d2, off);
            d3 += __shfl_xor_sync(0xffffffffu, d3, off);
        }
        if (cg == 0) g_e[rbase + r] = make_float4(d0, d1, d2, d3);
    }
}

// ---------------------------------------------------------------------------
// CSR build. g_cursor arrives zeroed (aggA tail of prior replay).
// ---------------------------------------------------------------------------
__global__ void k_hist(const int* __restrict__ ei) {
    int t = blockIdx.x * blockDim.x + threadIdx.x;
    if (t < EE) atomicAdd(&g_cursor[ei[EE + t]], 1);
}

// Single-kernel scan: 98 blocks (one wave). Each block publishes its total
// early (fence + flag), locally scans, then sums predecessor aggregates
// thread-parallel. Flags reset by fill's tail block.
__global__ void __launch_bounds__(SCAN_B) k_scanLB() {
    __shared__ int wtot[32];
    __shared__ int wscn[32];
    __shared__ int s_exoff;
    int t = threadIdx.x, b = blockIdx.x;
    int idx = b * SCAN_B + t;
    int lane = t & 31, w = t >> 5;
    int c = (idx < NN) ? g_cursor[idx] : 0;

    // 1) block total, publish aggregate ASAP
    int tot = c;
    #pragma unroll
    for (int o = 16; o; o >>= 1) tot += __shfl_xor_sync(0xffffffffu, tot, o);
    if (lane == 0) wtot[w] = tot;
    __syncthreads();
    if (w == 0) {
        int v = wtot[lane];
        #pragma unroll
        for (int o = 16; o; o >>= 1) v += __shfl_xor_sync(0xffffffffu, v, o);
        if (lane == 0) {
            *(volatile int*)&g_agg[b] = v;
            __threadfence();
            *(volatile int*)&g_flag[b] = 1;
        }
    }
    if (t == 0) s_exoff = 0;

    // 2) local inclusive scan
    int v = c;
    #pragma unroll
    for (int o = 1; o < 32; o <<= 1) {
        int n = __shfl_up_sync(0xffffffffu, v, o);
        if (lane >= o) v += n;
    }
    if (lane == 31) wscn[w] = v;
    __syncthreads();
    if (w == 0) {
        int sv = wscn[lane];
        #pragma unroll
        for (int o = 1; o < 32; o <<= 1) {
            int n = __shfl_up_sync(0xffffffffu, sv, o);
            if (lane >= o) sv += n;
        }
        wscn[lane] = sv;
    }
    __syncthreads();
    int incl = v + ((w > 0) ? wscn[w - 1] : 0);

    // 3) lookback: threads t < b wait on predecessor flags, sum aggregates
    if (t < b) {
        while (*(volatile int*)&g_flag[t] == 0) { }
        __threadfence();
        atomicAdd(&s_exoff, *(volatile int*)&g_agg[t]);
    }
    __syncthreads();
    int off = s_exoff;
    if (idx < NN) {
        int r = off + incl - c;
        g_rowptr[idx] = r;
        g_cursor[idx] = r;
    }
    if (idx == 0) g_rowptr[NN] = EE;
}

// fill + tail block resets scan flags for the next replay
__global__ void k_fill(const int* __restrict__ ei) {
    if (blockIdx.x >= FILL_BLOCKS) {
        int i = threadIdx.x;
        if (i < NBLK) g_flag[i] = 0;
        return;
    }
    int t = blockIdx.x * blockDim.x + threadIdx.x;
    if (t < EE) {
        int d = ei[EE + t];
        int p = atomicAdd(&g_cursor[d], 1);
        g_col[p] = ei[t];
    }
}

// ---------------------------------------------------------------------------
// Pass A: TWO nodes per warp (16-lane groups). Tail blocks zero g_cursor.
// ---------------------------------------------------------------------------
__global__ void __launch_bounds__(256) k_aggA() {
    if (blockIdx.x >= AGG16_BLOCKS) {
        int i = (blockIdx.x - AGG16_BLOCKS) * 256 + threadIdx.x;
        if (i < NN) g_cursor[i] = 0;
        return;
    }
    int grp = (blockIdx.x * 256 + threadIdx.x) >> 4;   // 16-lane group id
    int l16 = threadIdx.x & 15;
    if (grp >= NN) return;
    int s = g_rowptr[grp], e = g_rowptr[grp + 1];
    float s0 = 0.f, s1 = 0.f, s2 = 0.f;
    for (int p = s + l16; p < e; p += 16) {
        int j = __ldg(&g_col[p]);
        float4 ev = __ldg(&g_e[j]);
        s0 += ev.x; s1 += ev.y; s2 += ev.z;
    }
    #pragma unroll
    for (int o = 8; o; o >>= 1) {
        s0 += __shfl_xor_sync(0xffffffffu, s0, o);
        s1 += __shfl_xor_sync(0xffffffffu, s1, o);
        s2 += __shfl_xor_sync(0xffffffffu, s2, o);
    }
    if (l16 == 0) {
        float r0 = fmaxf(s0, 0.f), r1 = fmaxf(s1, 0.f);
        float p1 = 1.0f / (1.0f + expf(r0 - r1));
        float sel = (p1 > THRESH) ? 1.0f : 0.0f;
        g_sel[grp]  = sel;
        g_b1[grp]   = s2;
        float d     = __ldg(&g_e[grp]).w;
        g_selD[grp] = sel * d;
    }
}

// ---------------------------------------------------------------------------
// Pass B: TWO nodes per warp (16-lane groups). 4B gathers.
// ---------------------------------------------------------------------------
__global__ void __launch_bounds__(256) k_aggB() {
    int grp = (blockIdx.x * 256 + threadIdx.x) >> 4;
    int l16 = threadIdx.x & 15;
    if (grp >= NN) return;
    int s = g_rowptr[grp], e = g_rowptr[grp + 1];
    float z = 0.f;
    for (int p = s + l16; p < e; p += 16)
        z += __ldg(&g_selD[__ldg(&g_col[p])]);
    #pragma unroll
    for (int o = 8; o; o >>= 1) z += __shfl_xor_sync(0xffffffffu, z, o);
    if (l16 == 0) {
        z += g_b1[grp];
        float ws = 1.0f / (1.0f + expf(-z));
        g_gate[grp] = ws * g_sel[grp];
    }
}

// ---------------------------------------------------------------------------
// Pass C: edge-paired half-warp gather (proven structure, unchanged).
// ---------------------------------------------------------------------------
__global__ void __launch_bounds__(256) k_aggC(float* __restrict__ out) {
    int gw = (blockIdx.x * blockDim.x + threadIdx.x) >> 5;
    int lane = threadIdx.x & 31;
    if (gw >= NN) return;
    int s = g_rowptr[gw], e = g_rowptr[gw + 1];
    const float4* U4 = (const float4*)g_updated;
    int half = lane >> 4;
    int hl   = lane & 15;
    u64 acc0 = 0, acc1 = 0;

    for (int base = s; base < e; base += 32) {
        int cnt = e - base; if (cnt > 32) cnt = 32;
        int jreg = 0; float greg = 0.f;
        if (lane < cnt) {
            jreg = __ldg(&g_col[base + lane]);
            greg = __ldg(&g_gate[jreg]);
        }
        int cnt2 = (cnt + 1) & ~1;
        for (int q = 0; q < cnt2; q += 2) {
            int myq = q + half;
            int   j = __shfl_sync(0xffffffffu, jreg, myq);
            float g = __shfl_sync(0xffffffffu, greg, myq);
            if (g != 0.f) {
                float4 u = __ldg(&U4[(size_t)j * 16 + hl]);
                u64 gg = pack2(g, g);
                acc0 = fma2(gg, pack2(u.x, u.y), acc0);
                acc1 = fma2(gg, pack2(u.z, u.w), acc1);
            }
        }
    }
    acc0 = add2(acc0, __shfl_xor_sync(0xffffffffu, acc0, 16));
    acc1 = add2(acc1, __shfl_xor_sync(0xffffffffu, acc1, 16));
    float a0, a1, a2, a3;
    unpack2(acc0, a0, a1);
    unpack2(acc1, a2, a3);

    float4 ui = __ldg(&U4[(size_t)gw * 16 + hl]);
    float o0 = ui.x + fmaxf(a0, 0.f);
    float o1 = ui.y + fmaxf(a1, 0.f);
    float o2 = ui.z + fmaxf(a2, 0.f);
    float o3 = ui.w + fmaxf(a3, 0.f);
    float ss = o0 * o0 + o1 * o1 + o2 * o2 + o3 * o3;
    #pragma unroll
    for (int o = 8; o; o >>= 1) ss += __shfl_xor_sync(0xffffffffu, ss, o);
    float n = fmaxf(sqrtf(ss), 1e-15f);
    float th = tanhf(n);
    float f = (th > MAXN) ? (MAXN / n) : (th / n);
    if (half == 0)
        ((float4*)out)[(size_t)gw * 16 + hl] =
            make_float4(o0 * f, o1 * f, o2 * f, o3 * f);
}

// ---------------------------------------------------------------------------
extern "C" void kernel_launch(void* const* d_in, const int* in_sizes, int n_in,
                              void* d_out, int out_size) {
    const float* x   = (const float*)d_in[0];
    const int*   ei  = (const int*)  d_in[1];
    const float* Wup = (const float*)d_in[2];
    const float* Wpl = (const float*)d_in[3];
    const float* Wlw = (const float*)d_in[4];
    float* out = (float*)d_out;

    (void)in_sizes; (void)n_in; (void)out_size;

    k_hist<<<FILL_BLOCKS, 256>>>(ei);          // 1
    k_scanLB<<<NBLK, SCAN_B>>>();              // 2
    k_up<<<GEMM_BLOCKS, GEMM_TPB>>>(x, Wup, Wpl, Wlw);  // 3 (indep of 1-2)
    k_fill<<<FILL_BLOCKS + 1, 256>>>(ei);      // 4  <- profiled slot
    k_aggA<<<AGG16_BLOCKS + CZERO_BLOCKS, 256>>>();     // 5
    k_aggB<<<AGG16_BLOCKS, 256>>>();           // 6
    k_aggC<<<AGG32_BLOCKS, 256>>>(out);        // 7
}

// round 17
// speedup vs baseline: 1.1143x; 1.0517x over previous
#include <cuda_runtime.h>
#include <math.h>

#define NN   100000
#define EE   1600000
#define FIN  128
#define FOUT 64
#define THRESH 0.48f
#define MAXN   (1.0f - 4e-3f)

#define SCAN_B 1024
#define NBLK   ((NN + SCAN_B - 1) / SCAN_B)   // 98

#define GEMM_ROWS   32
#define GEMM_TPB    128
#define GEMM_BLOCKS (NN / GEMM_ROWS)          // 3125; threads = 400000 = EE/4

#define FILLV_BLOCKS ((EE / 4 + 255) / 256)   // 1563
#define AGG16_BLOCKS ((NN * 16 + 255) / 256)  // 6250 (two nodes/warp passes)
#define AGG32_BLOCKS ((NN * 32 + 255) / 256)  // 12500 (pass C)

typedef unsigned long long u64;

// -------- scratch (device globals; zero-initialized at load) --------
__device__ float  g_updated [NN * FOUT];
__device__ float4 g_e       [NN];   // (u.wpl0, u.wpl1, u.wlw_hi, u.wlw_lo)
__device__ float  g_b1      [NN];
__device__ float  g_sel     [NN];
__device__ float  g_selD    [NN];
__device__ float  g_gate    [NN];
__device__ int    g_rowptr  [NN + 1];
__device__ int    g_cursor  [NN];   // self-restoring: zeroed by scanLB
__device__ int    g_col     [EE];
__device__ int    g_rank    [EE];   // per-edge within-node rank (from k_up)
__device__ int    g_agg     [NBLK]; // scan lookback aggregates
__device__ int    g_flag    [NBLK]; // self-restoring: zeroed by fill tail

// ---- f32x2 helpers ----
__device__ __forceinline__ u64 pack2(float lo, float hi) {
    u64 r; asm("mov.b64 %0,{%1,%2};" : "=l"(r) : "f"(lo), "f"(hi)); return r;
}
__device__ __forceinline__ void unpack2(u64 v, float& lo, float& hi) {
    asm("mov.b64 {%0,%1},%2;" : "=f"(lo), "=f"(hi) : "l"(v));
}
__device__ __forceinline__ u64 add2(u64 a, u64 b) {
    u64 d; asm("add.rn.f32x2 %0,%1,%2;" : "=l"(d) : "l"(a), "l"(b)); return d;
}
__device__ __forceinline__ u64 fma2(u64 a, u64 b, u64 c) {
    u64 d; asm("fma.rn.f32x2 %0,%1,%2,%3;" : "=l"(d) : "l"(a), "l"(b), "l"(c)); return d;
}

// ---------------------------------------------------------------------------
// K1: fused edge-histogram (4 edges/thread, atomic returns = ranks; latency
// hidden under GEMM) + logmap0 + GEMM + leaky_relu + projection epilogue.
// ---------------------------------------------------------------------------
__global__ void __launch_bounds__(GEMM_TPB) k_up(const float* __restrict__ x,
                                                 const float* __restrict__ Wup,
                                                 const float* __restrict__ Wpl,
                                                 const float* __restrict__ Wlw,
                                                 const int* __restrict__ ei) {
    // ---- hist: issue early; results consumed only at the end ----
    int gid = blockIdx.x * GEMM_TPB + threadIdx.x;          // 0..399999
    int4 d4 = __ldg((const int4*)(ei + EE) + gid);
    int hr0 = atomicAdd(&g_cursor[d4.x], 1);
    int hr1 = atomicAdd(&g_cursor[d4.y], 1);
    int hr2 = atomicAdd(&g_cursor[d4.z], 1);
    int hr3 = atomicAdd(&g_cursor[d4.w], 1);

    __shared__ float  xs[GEMM_ROWS][FIN];   // 16 KB
    __shared__ float4 Ws[FIN * 16];         // 32 KB

    int t = threadIdx.x;
    int rbase = blockIdx.x * GEMM_ROWS;

    const float4* W4 = (const float4*)Wup;
    #pragma unroll
    for (int i = t; i < FIN * 16; i += GEMM_TPB) Ws[i] = W4[i];
    const float4* x4 = (const float4*)(x + (size_t)rbase * FIN);
    float4* xs4 = (float4*)xs;
    #pragma unroll
    for (int i = t; i < GEMM_ROWS * FIN / 4; i += GEMM_TPB) xs4[i] = x4[i];
    __syncthreads();

    int w = t >> 5, lane = t & 31;
    #pragma unroll
    for (int rr = 0; rr < 8; ++rr) {
        int r = w * 8 + rr;
        float4 v = ((float4*)xs[r])[lane];
        float s = v.x * v.x + v.y * v.y + v.z * v.z + v.w * v.w;
        #pragma unroll
        for (int o = 16; o; o >>= 1) s += __shfl_xor_sync(0xffffffffu, s, o);
        float n = fmaxf(sqrtf(s), 1e-15f);
        float a = fminf(fmaxf(n, -1.0f + 1e-7f), 1.0f - 1e-7f);
        float art = 0.5f * (log1pf(a) - log1pf(-a));
        float sc = art / n;
        v.x *= sc; v.y *= sc; v.z *= sc; v.w *= sc;
        ((float4*)xs[r])[lane] = v;
    }
    __syncthreads();

    int cg = t & 15;
    int rg = t >> 4;
    u64 acc[4][2];
    #pragma unroll
    for (int i = 0; i < 4; ++i) { acc[i][0] = 0; acc[i][1] = 0; }

    #pragma unroll 2
    for (int k = 0; k < FIN; k += 4) {
        float4 xv[4];
        #pragma unroll
        for (int i = 0; i < 4; ++i)
            xv[i] = *(const float4*)&xs[rg + 8 * i][k];
        #pragma unroll
        for (int q = 0; q < 4; ++q) {
            float4 wv = Ws[(k + q) * 16 + cg];
            u64 w01 = pack2(wv.x, wv.y);
            u64 w23 = pack2(wv.z, wv.w);
            #pragma unroll
            for (int i = 0; i < 4; ++i) {
                float xq = (q == 0) ? xv[i].x : (q == 1) ? xv[i].y
                         : (q == 2) ? xv[i].z : xv[i].w;
                u64 xx = pack2(xq, xq);
                acc[i][0] = fma2(xx, w01, acc[i][0]);
                acc[i][1] = fma2(xx, w23, acc[i][1]);
            }
        }
    }

    float4 we[4];
    #pragma unroll
    for (int m = 0; m < 4; ++m) {
        int c = cg * 4 + m;
        we[m] = make_float4(__ldg(&Wpl[2 * c]), __ldg(&Wpl[2 * c + 1]),
                            __ldg(&Wlw[64 + c]), __ldg(&Wlw[c]));
    }

    #pragma unroll
    for (int i = 0; i < 4; ++i) {
        int r = rg + 8 * i;
        float c0, c1, c2, c3;
        unpack2(acc[i][0], c0, c1);
        unpack2(acc[i][1], c2, c3);
        float4 o;
        o.x = c0 > 0.f ? c0 : 0.01f * c0;
        o.y = c1 > 0.f ? c1 : 0.01f * c1;
        o.z = c2 > 0.f ? c2 : 0.01f * c2;
        o.w = c3 > 0.f ? c3 : 0.01f * c3;
        ((float4*)g_updated)[(size_t)(rbase + r) * 16 + cg] = o;

        float d0 = o.x * we[0].x + o.y * we[1].x + o.z * we[2].x + o.w * we[3].x;
        float d1 = o.x * we[0].y + o.y * we[1].y + o.z * we[2].y + o.w * we[3].y;
        float d2 = o.x * we[0].z + o.y * we[1].z + o.z * we[2].z + o.w * we[3].z;
        float d3 = o.x * we[0].w + o.y * we[1].w + o.z * we[2].w + o.w * we[3].w;
        #pragma unroll
        for (int off = 8; off; off >>= 1) {
            d0 += __shfl_xor_sync(0xffffffffu, d0, off);
            d1 += __shfl_xor_sync(0xffffffffu, d1, off);
            d2 += __shfl_xor_sync(0xffffffffu, d2, off);
            d3 += __shfl_xor_sync(0xffffffffu, d3, off);
        }
        if (cg == 0) g_e[rbase + r] = make_float4(d0, d1, d2, d3);
    }

    // ---- hist ranks: store (coalesced); atomic latency long hidden ----
    ((int4*)g_rank)[gid] = make_int4(hr0, hr1, hr2, hr3);
}

// ---------------------------------------------------------------------------
// Single-kernel lookback scan: counts -> rowptr; re-zeroes g_cursor for the
// next replay (it is the last cursor reader now).
// ---------------------------------------------------------------------------
__global__ void __launch_bounds__(SCAN_B) k_scanLB() {
    __shared__ int wtot[32];
    __shared__ int wscn[32];
    __shared__ int s_exoff;
    int t = threadIdx.x, b = blockIdx.x;
    int idx = b * SCAN_B + t;
    int lane = t & 31, w = t >> 5;
    int c = (idx < NN) ? g_cursor[idx] : 0;
    if (idx < NN) g_cursor[idx] = 0;       // restore for next replay

    int tot = c;
    #pragma unroll
    for (int o = 16; o; o >>= 1) tot += __shfl_xor_sync(0xffffffffu, tot, o);
    if (lane == 0) wtot[w] = tot;
    __syncthreads();
    if (w == 0) {
        int v = wtot[lane];
        #pragma unroll
        for (int o = 16; o; o >>= 1) v += __shfl_xor_sync(0xffffffffu, v, o);
        if (lane == 0) {
            *(volatile int*)&g_agg[b] = v;
            __threadfence();
            *(volatile int*)&g_flag[b] = 1;
        }
    }
    if (t == 0) s_exoff = 0;

    int v = c;
    #pragma unroll
    for (int o = 1; o < 32; o <<= 1) {
        int n = __shfl_up_sync(0xffffffffu, v, o);
        if (lane >= o) v += n;
    }
    if (lane == 31) wscn[w] = v;
    __syncthreads();
    if (w == 0) {
        int sv = wscn[lane];
        #pragma unroll
        for (int o = 1; o < 32; o <<= 1) {
            int n = __shfl_up_sync(0xffffffffu, sv, o);
            if (lane >= o) sv += n;
        }
        wscn[lane] = sv;
    }
    __syncthreads();
    int incl = v + ((w > 0) ? wscn[w - 1] : 0);

    if (t < b) {
        while (*(volatile int*)&g_flag[t] == 0) { }
        __threadfence();
        atomicAdd(&s_exoff, *(volatile int*)&g_agg[t]);
    }
    __syncthreads();
    if (idx < NN) g_rowptr[idx] = s_exoff + incl - c;
    if (idx == 0) g_rowptr[NN] = EE;
}

// ---------------------------------------------------------------------------
// fill, atomic-free: g_col[rowptr[dst] + rank] = src. 4 edges/thread.
// Tail block resets scan flags for the next replay.
// ---------------------------------------------------------------------------
__global__ void k_fill(const int* __restrict__ ei) {
    if (blockIdx.x >= FILLV_BLOCKS) {
        if (threadIdx.x < NBLK) g_flag[threadIdx.x] = 0;
        return;
    }
    int gid = blockIdx.x * 256 + threadIdx.x;
    if (gid < EE / 4) {
        int4 s4 = __ldg((const int4*)ei + gid);
        int4 d4 = __ldg((const int4*)(ei + EE) + gid);
        int4 r4 = __ldg((const int4*)g_rank + gid);
        g_col[__ldg(&g_rowptr[d4.x]) + r4.x] = s4.x;
        g_col[__ldg(&g_rowptr[d4.y]) + r4.y] = s4.y;
        g_col[__ldg(&g_rowptr[d4.z]) + r4.z] = s4.z;
        g_col[__ldg(&g_rowptr[d4.w]) + r4.w] = s4.w;
    }
}

// ---------------------------------------------------------------------------
// Pass A: two nodes per warp (16-lane groups); 16B projection gathers.
// ---------------------------------------------------------------------------
__global__ void __launch_bounds__(256) k_aggA() {
    int grp = (blockIdx.x * 256 + threadIdx.x) >> 4;
    int l16 = threadIdx.x & 15;
    if (grp >= NN) return;
    int s = g_rowptr[grp], e = g_rowptr[grp + 1];
    float s0 = 0.f, s1 = 0.f, s2 = 0.f;
    for (int p = s + l16; p < e; p += 16) {
        int j = __ldg(&g_col[p]);
        float4 ev = __ldg(&g_e[j]);
        s0 += ev.x; s1 += ev.y; s2 += ev.z;
    }
    #pragma unroll
    for (int o = 8; o; o >>= 1) {
        s0 += __shfl_xor_sync(0xffffffffu, s0, o);
        s1 += __shfl_xor_sync(0xffffffffu, s1, o);
        s2 += __shfl_xor_sync(0xffffffffu, s2, o);
    }
    if (l16 == 0) {
        float r0 = fmaxf(s0, 0.f), r1 = fmaxf(s1, 0.f);
        float p1 = 1.0f / (1.0f + expf(r0 - r1));
        float sel = (p1 > THRESH) ? 1.0f : 0.0f;
        g_sel[grp]  = sel;
        g_b1[grp]   = s2;
        float d     = __ldg(&g_e[grp]).w;
        g_selD[grp] = sel * d;
    }
}

// ---------------------------------------------------------------------------
// Pass B: two nodes per warp; 4B gathers.
// ---------------------------------------------------------------------------
__global__ void __launch_bounds__(256) k_aggB() {
    int grp = (blockIdx.x * 256 + threadIdx.x) >> 4;
    int l16 = threadIdx.x & 15;
    if (grp >= NN) return;
    int s = g_rowptr[grp], e = g_rowptr[grp + 1];
    float z = 0.f;
    for (int p = s + l16; p < e; p += 16)
        z += __ldg(&g_selD[__ldg(&g_col[p])]);
    #pragma unroll
    for (int o = 8; o; o >>= 1) z += __shfl_xor_sync(0xffffffffu, z, o);
    if (l16 == 0) {
        z += g_b1[grp];
        float ws = 1.0f / (1.0f + expf(-z));
        g_gate[grp] = ws * g_sel[grp];
    }
}

// ---------------------------------------------------------------------------
// Pass C: edge-paired half-warp gather (proven structure, unchanged).
// ---------------------------------------------------------------------------
__global__ void __launch_bounds__(256) k_aggC(float* __restrict__ out) {
    int gw = (blockIdx.x * blockDim.x + threadIdx.x) >> 5;
    int lane = threadIdx.x & 31;
    if (gw >= NN) return;
    int s = g_rowptr[gw], e = g_rowptr[gw + 1];
    const float4* U4 = (const float4*)g_updated;
    int half = lane >> 4;
    int hl   = lane & 15;
    u64 acc0 = 0, acc1 = 0;

    for (int base = s; base < e; base += 32) {
        int cnt = e - base; if (cnt > 32) cnt = 32;
        int jreg = 0; float greg = 0.f;
        if (lane < cnt) {
            jreg = __ldg(&g_col[base + lane]);
            greg = __ldg(&g_gate[jreg]);
        }
        int cnt2 = (cnt + 1) & ~1;
        for (int q = 0; q < cnt2; q += 2) {
            int myq = q + half;
            int   j = __shfl_sync(0xffffffffu, jreg, myq);
            float g = __shfl_sync(0xffffffffu, greg, myq);
            if (g != 0.f) {
                float4 u = __ldg(&U4[(size_t)j * 16 + hl]);
                u64 gg = pack2(g, g);
                acc0 = fma2(gg, pack2(u.x, u.y), acc0);
                acc1 = fma2(gg, pack2(u.z, u.w), acc1);
            }
        }
    }
    acc0 = add2(acc0, __shfl_xor_sync(0xffffffffu, acc0, 16));
    acc1 = add2(acc1, __shfl_xor_sync(0xffffffffu, acc1, 16));
    float a0, a1, a2, a3;
    unpack2(acc0, a0, a1);
    unpack2(acc1, a2, a3);

    float4 ui = __ldg(&U4[(size_t)gw * 16 + hl]);
    float o0 = ui.x + fmaxf(a0, 0.f);
    float o1 = ui.y + fmaxf(a1, 0.f);
    float o2 = ui.z + fmaxf(a2, 0.f);
    float o3 = ui.w + fmaxf(a3, 0.f);
    float ss = o0 * o0 + o1 * o1 + o2 * o2 + o3 * o3;
    #pragma unroll
    for (int o = 8; o; o >>= 1) ss += __shfl_xor_sync(0xffffffffu, ss, o);
    float n = fmaxf(sqrtf(ss), 1e-15f);
    float th = tanhf(n);
    float f = (th > MAXN) ? (MAXN / n) : (th / n);
    if (half == 0)
        ((float4*)out)[(size_t)gw * 16 + hl] =
            make_float4(o0 * f, o1 * f, o2 * f, o3 * f);
}

// ---------------------------------------------------------------------------
extern "C" void kernel_launch(void* const* d_in, const int* in_sizes, int n_in,
                              void* d_out, int out_size) {
    const float* x   = (const float*)d_in[0];
    const int*   ei  = (const int*)  d_in[1];
    const float* Wup = (const float*)d_in[2];
    const float* Wpl = (const float*)d_in[3];
    const float* Wlw = (const float*)d_in[4];
    float* out = (float*)d_out;

    (void)in_sizes; (void)n_in; (void)out_size;

    k_up<<<GEMM_BLOCKS, GEMM_TPB>>>(x, Wup, Wpl, Wlw, ei);  // 1: GEMM + hist
    k_scanLB<<<NBLK, SCAN_B>>>();                           // 2
    k_fill<<<FILLV_BLOCKS + 1, 256>>>(ei);                  // 3 (atomic-free)
    k_aggA<<<AGG16_BLOCKS, 256>>>();                        // 4 <- profiled
    k_aggB<<<AGG16_BLOCKS, 256>>>();                        // 5
    k_aggC<<<AGG32_BLOCKS, 256>>>(out);                     // 6
}